// round 15
// baseline (speedup 1.0000x reference)
#include <cuda_runtime.h>
#include <cuda_fp16.h>
#include <stdint.h>

#define NPTS   65536
#define CCH    512
#define NH     8
#define PW     128
#define DHD    64
#define RPEN   31
#define PBND   15
#define SCALE  0.125f

// ---------------------------------------------------------------------------
// Static device scratch (fp16)
// ---------------------------------------------------------------------------
__device__ __half g_qkv[(size_t)NPTS * 1536];   // serialized qkv, single fp16
__device__ __half g_fa [(size_t)NPTS * 512];    // feat[order], single fp16
__device__ __half g_wq [1536 * 512];            // w_qkv single fp16
__device__ __half g_wp [512 * 512];             // w_proj single fp16

// ---------------------------------------------------------------------------
// PTX helpers (sm_100-legal)
// ---------------------------------------------------------------------------
__device__ __forceinline__ uint32_t smem_u32(const void* p) {
    uint32_t a;
    asm("{ .reg .u64 t; cvta.to.shared.u64 t, %1; cvt.u32.u64 %0, t; }"
        : "=r"(a) : "l"(p));
    return a;
}
__device__ __forceinline__ void cp16(uint32_t dst, const void* src) {
    asm volatile("cp.async.cg.shared.global [%0], [%1], 16;"
                 :: "r"(dst), "l"(src) : "memory");
}
__device__ __forceinline__ void cp_commit() {
    asm volatile("cp.async.commit_group;" ::: "memory");
}
template <int N>
__device__ __forceinline__ void cp_wait() {
    asm volatile("cp.async.wait_group %0;" :: "n"(N) : "memory");
}
__device__ __forceinline__ void ldm_x4(uint32_t* r, uint32_t addr) {
    asm volatile("ldmatrix.sync.aligned.m8n8.x4.shared.b16 {%0,%1,%2,%3}, [%4];"
                 : "=r"(r[0]), "=r"(r[1]), "=r"(r[2]), "=r"(r[3]) : "r"(addr));
}
__device__ __forceinline__ void ldm_x4_t(uint32_t* r, uint32_t addr) {
    asm volatile("ldmatrix.sync.aligned.m8n8.x4.trans.shared.b16 {%0,%1,%2,%3}, [%4];"
                 : "=r"(r[0]), "=r"(r[1]), "=r"(r[2]), "=r"(r[3]) : "r"(addr));
}
__device__ __forceinline__ void mma_f16(float* d, const uint32_t* a, const uint32_t* b) {
    asm volatile(
        "mma.sync.aligned.m16n8k16.row.col.f32.f16.f16.f32 "
        "{%0,%1,%2,%3}, {%4,%5,%6,%7}, {%8,%9}, {%0,%1,%2,%3};"
        : "+f"(d[0]), "+f"(d[1]), "+f"(d[2]), "+f"(d[3])
        : "r"(a[0]), "r"(a[1]), "r"(a[2]), "r"(a[3]), "r"(b[0]), "r"(b[1]));
}

// ---------------------------------------------------------------------------
// fp16 conversion kernels
// ---------------------------------------------------------------------------
__global__ void tohalf_gather_k(const float* __restrict__ src, const int* __restrict__ gidx,
                                __half* __restrict__ dst)
{
    int i = blockIdx.x * 256 + threadIdx.x;
    int m = i >> 7;
    int c = (i & 127) << 2;
    float4 v = *(const float4*)(src + (size_t)gidx[m] * 512 + c);
    __align__(8) __half hb[4];
    hb[0] = __float2half_rn(v.x); hb[1] = __float2half_rn(v.y);
    hb[2] = __float2half_rn(v.z); hb[3] = __float2half_rn(v.w);
    *(uint2*)(dst + (size_t)m * 512 + c) = *(uint2*)hb;
}

__global__ void tohalf_plain_k(const float* __restrict__ src, __half* __restrict__ dst, int n4)
{
    int i = blockIdx.x * 256 + threadIdx.x;
    if (i >= n4) return;
    float4 v = *(const float4*)(src + (size_t)i * 4);
    __align__(8) __half hb[4];
    hb[0] = __float2half_rn(v.x); hb[1] = __float2half_rn(v.y);
    hb[2] = __float2half_rn(v.z); hb[3] = __float2half_rn(v.w);
    *(uint2*)(dst + (size_t)i * 4) = *(uint2*)hb;
}

// ---------------------------------------------------------------------------
// fp16 1-term GEMM (R13 best-measured, unchanged): C = A B^T + bias.
// K=512, CTA tile 128x128, BK=64, 4 warps @ 64x64, 2-stage pipeline.
// ---------------------------------------------------------------------------
#define GK       512
#define BK       64
#define NCH      (GK / BK)
#define TROW_B   144
#define TILE_B   (128 * TROW_B)
#define STAGE_B  (2 * TILE_B)
#define GSMEM    (2 * STAGE_B)

__global__ __launch_bounds__(128, 2)
void gemm_f16(const __half* __restrict__ A, const __half* __restrict__ B0,
              const float* __restrict__ bias, float* __restrict__ C,
              __half* __restrict__ Chalf, int Ntot)
{
    extern __shared__ __align__(128) char sm[];
    const uint32_t smb = smem_u32(sm);

    const int tid  = threadIdx.x;
    const int lane = tid & 31;
    const int warp = tid >> 5;
    const int wm   = warp >> 1;
    const int wn   = warp & 1;
    const int m0   = blockIdx.y * 128;
    const int n0   = blockIdx.x * 128;

    const __half* gsrc[2] = { A + (size_t)m0 * GK, B0 + (size_t)n0 * GK };

    auto load_stage = [&](int c) {
        const uint32_t sb = smb + (c & 1) * STAGE_B;
#pragma unroll
        for (int t = 0; t < 2; t++) {
            const __half* g = gsrc[t] + c * BK;
#pragma unroll
            for (int i = 0; i < 8; i++) {
                int idx = i * 128 + tid;
                int r = idx >> 3, s = idx & 7;
                cp16(sb + t * TILE_B + r * TROW_B + s * 16,
                     g + (size_t)r * GK + s * 8);
            }
        }
    };

    float acc[4][8][4];
#pragma unroll
    for (int i = 0; i < 4; i++)
#pragma unroll
        for (int j = 0; j < 8; j++)
#pragma unroll
            for (int e = 0; e < 4; e++) acc[i][j][e] = 0.f;

    const int arow  = lane & 15;
    const int acolb = (lane >> 4) * 16;
    const int brow  = (lane & 7) + (lane >> 4) * 8;
    const int bkb   = ((lane >> 3) & 1) * 16;

    load_stage(0);
    cp_commit();

    for (int c = 0; c < NCH; c++) {
        if (c + 1 < NCH) { load_stage(c + 1); cp_commit(); cp_wait<1>(); }
        else             { cp_wait<0>(); }
        __syncthreads();

        const uint32_t sb  = smb + (c & 1) * STAGE_B;
        const uint32_t sA  = sb;
        const uint32_t sB0 = sb + TILE_B;

#pragma unroll
        for (int ks = 0; ks < 4; ks++) {
            const int kb = ks * 32;
            uint32_t ah[4][4], b0[4][4];
#pragma unroll
            for (int mi = 0; mi < 4; mi++)
                ldm_x4(ah[mi], sA + (wm * 64 + mi * 16 + arow) * TROW_B + kb + acolb);
#pragma unroll
            for (int jj = 0; jj < 4; jj++)
                ldm_x4(b0[jj], sB0 + (wn * 64 + jj * 16 + brow) * TROW_B + kb + bkb);
#pragma unroll
            for (int mi = 0; mi < 4; mi++)
#pragma unroll
                for (int nj = 0; nj < 8; nj++)
                    mma_f16(acc[mi][nj], ah[mi], &b0[nj >> 1][(nj & 1) * 2]);
        }
        if (c + 1 < NCH) __syncthreads();
    }

    const int gr = lane >> 2;
    const int gc = (lane & 3) * 2;
    float2 bv[8];
#pragma unroll
    for (int nj = 0; nj < 8; nj++)
        bv[nj] = *(const float2*)(bias + n0 + wn * 64 + nj * 8 + gc);

    if (Chalf) {
#pragma unroll
        for (int mi = 0; mi < 4; mi++) {
            int rowa = m0 + wm * 64 + mi * 16 + gr;
#pragma unroll
            for (int nj = 0; nj < 8; nj++) {
                int col = n0 + wn * 64 + nj * 8 + gc;
                __half2 h01, h23;
                h01.x = __float2half_rn(acc[mi][nj][0] + bv[nj].x);
                h01.y = __float2half_rn(acc[mi][nj][1] + bv[nj].y);
                h23.x = __float2half_rn(acc[mi][nj][2] + bv[nj].x);
                h23.y = __float2half_rn(acc[mi][nj][3] + bv[nj].y);
                *(__half2*)(Chalf + (size_t)rowa * Ntot + col)       = h01;
                *(__half2*)(Chalf + (size_t)(rowa + 8) * Ntot + col) = h23;
            }
        }
    } else {
#pragma unroll
        for (int mi = 0; mi < 4; mi++) {
            int rowa = m0 + wm * 64 + mi * 16 + gr;
#pragma unroll
            for (int nj = 0; nj < 8; nj++) {
                int col = n0 + wn * 64 + nj * 8 + gc;
                float2 lo = make_float2(acc[mi][nj][0] + bv[nj].x, acc[mi][nj][1] + bv[nj].y);
                float2 hi = make_float2(acc[mi][nj][2] + bv[nj].x, acc[mi][nj][3] + bv[nj].y);
                *(float2*)(C + (size_t)rowa * Ntot + col)       = lo;
                *(float2*)(C + (size_t)(rowa + 8) * Ntot + col) = hi;
            }
        }
    }
}

// ---------------------------------------------------------------------------
// FUSED attention + output projection. One CTA per window (512 CTAs, 256 thr).
// Head loop (8 heads = 8 GEMM3 k-chunks, identical accumulation order) fills
// a smem O-matrix [128 x 512] fp16; then the projection streams w_proj tiles
// through the dead K/V stages and writes final f32 rows scattered by order.
// ---------------------------------------------------------------------------
#define ARS      144
#define ORS      1040                          // O row stride (bank phase 4/row)
#define AT_B     (128 * ARS)                   // 18432
#define OFF_O    0                             // 128*1040 = 133120
#define OFF_KV   133120                        // 2 stages x (K|V) = 4*18432
#define OFF_QB   (OFF_KV + 4 * AT_B)           // 206848
#define OFF_RPE  (OFF_QB + AT_B)               // 225280: 744 f32 (rpe, global layout)
#define OFF_RPH  (OFF_RPE + 744 * 4)           // 228256: 93 f32 per-head slice
#define OFF_PC   (OFF_RPH + 93 * 4 + 4)       // 228632: packed coords 128 u32
#define OFF_ORD2 (OFF_PC + 128 * 4)            // 229144
#define FSMEM    (OFF_ORD2 + 128 * 4)          // 229656 <= 232448

__global__ __launch_bounds__(256, 1)
void attn_proj(const __half* __restrict__ qkv,
               const int* __restrict__ order, const int* __restrict__ gcoord,
               const float* __restrict__ rpe, const __half* __restrict__ wp,
               const float* __restrict__ bproj, float* __restrict__ dout)
{
    extern __shared__ __align__(128) char sm[];
    const uint32_t smb = smem_u32(sm);
    float*    rpeA = (float*)(sm + OFF_RPE);
    float*    rpeH = (float*)(sm + OFF_RPH);
    uint32_t* pcs  = (uint32_t*)(sm + OFF_PC);
    int*      ords = (int*)(sm + OFF_ORD2);

    const int w    = blockIdx.x;
    const int tid  = threadIdx.x;
    const int lane = tid & 31;
    const int wid  = tid >> 5;
    const int wb   = w * PW;

    // ---- coords / order / rpe (all heads) ----
    for (int i = tid; i < 128; i += 256) {
        int g = order[wb + i];
        ords[i] = g;
        uint32_t x = (uint32_t)gcoord[g * 3 + 0] & 0xFF;
        uint32_t y = (uint32_t)gcoord[g * 3 + 1] & 0xFF;
        uint32_t z = (uint32_t)gcoord[g * 3 + 2] & 0xFF;
        pcs[i] = x | (y << 8) | (z << 16);
    }
    for (int i = tid; i < 3 * RPEN * NH; i += 256) rpeA[i] = rpe[i];

    // per-head QKV stage loader: Q -> Qbuf, K/V -> stage (h&1)
    auto load_head = [&](int h) {
        const __half* base = qkv + (size_t)wb * 1536 + h * 64;
        const uint32_t kb = smb + OFF_KV + (h & 1) * (2 * AT_B);
        const __half* srcs[3] = { base, base + 512, base + 1024 };
        const uint32_t dsts[3] = { smb + OFF_QB, kb, kb + AT_B };
#pragma unroll
        for (int m = 0; m < 3; m++) {
#pragma unroll
            for (int i = 0; i < 4; i++) {
                int idx = i * 256 + tid;
                int r = idx >> 3, s = idx & 7;
                cp16(dsts[m] + r * ARS + s * 16, srcs[m] + (size_t)r * 1536 + s * 8);
            }
        }
    };

    load_head(0);
    cp_commit();

    const int arow  = lane & 15;
    const int acolb = (lane >> 4) * 16;
    const int brow  = (lane & 7) + (lane >> 4) * 8;
    const int bkb   = ((lane >> 3) & 1) * 16;
    const int w16   = wid * 16;
    const int gr    = lane >> 2;
    const int gc2   = (lane & 3) * 2;
    const int r1    = w16 + gr, r2 = r1 + 8;
    const int vrow  = ((lane >> 3) & 1) * 8 + (lane & 7);
    const int vcb   = (lane >> 4) * 16;
    const uint32_t NEG15 = 0xF1F1F1F1u, POS15 = 0x0F0F0F0Fu;

    for (int h = 0; h < NH; h++) {
        cp_wait<0>();          // group(h) landed (only one in flight)
        __syncthreads();       // publish stage + Qbuf (+ coords/rpe on h=0)

        // per-head rpe slice (93 floats) — written before 2nd barrier
        if (tid < 3 * RPEN) rpeH[tid] = rpeA[tid * NH + h];

        // Q fragments register-resident; Q buffer dead afterwards
        uint32_t q4[4][4];
#pragma unroll
        for (int ks = 0; ks < 4; ks++)
            ldm_x4(q4[ks], smb + OFF_QB + (w16 + arow) * ARS + ks * 32 + acolb);
        __syncthreads();       // Q reads done + rpeH published

        if (h + 1 < NH) { load_head(h + 1); cp_commit(); }

        const uint32_t kbase = smb + OFF_KV + (h & 1) * (2 * AT_B);
        const uint32_t vbase = kbase + AT_B;

        // ---- S = QK^T ----
        float s[16][4];
#pragma unroll
        for (int nj = 0; nj < 16; nj++)
#pragma unroll
            for (int e = 0; e < 4; e++) s[nj][e] = 0.f;
#pragma unroll
        for (int ks = 0; ks < 4; ks++) {
#pragma unroll
            for (int ng = 0; ng < 8; ng++) {
                uint32_t kk[4];
                ldm_x4(kk, kbase + (ng * 16 + brow) * ARS + ks * 32 + bkb);
                mma_f16(s[2 * ng],     q4[ks], kk + 0);
                mma_f16(s[2 * ng + 1], q4[ks], kk + 2);
            }
        }

        // ---- scale + RPE bias ----
        const uint32_t pq1 = pcs[r1], pq2 = pcs[r2];
#pragma unroll
        for (int nj = 0; nj < 16; nj++) {
            int c0 = nj * 8 + gc2;
#pragma unroll
            for (int cc = 0; cc < 2; cc++) {
                uint32_t pk = pcs[c0 + cc];
                uint32_t da = __vadd4(__vmins4(__vmaxs4(__vsubss4(pq1, pk), NEG15), POS15), POS15);
                uint32_t db = __vadd4(__vmins4(__vmaxs4(__vsubss4(pq2, pk), NEG15), POS15), POS15);
                float ba = rpeH[da & 0xFF] + rpeH[((da >> 8) & 0xFF) + RPEN]
                         + rpeH[((da >> 16) & 0xFF) + 2 * RPEN];
                float bb = rpeH[db & 0xFF] + rpeH[((db >> 8) & 0xFF) + RPEN]
                         + rpeH[((db >> 16) & 0xFF) + 2 * RPEN];
                s[nj][cc]     = s[nj][cc]     * SCALE + ba;
                s[nj][2 + cc] = s[nj][2 + cc] * SCALE + bb;
            }
        }

        // ---- softmax ----
        float m1 = -1e30f, m2 = -1e30f;
#pragma unroll
        for (int nj = 0; nj < 16; nj++) {
            m1 = fmaxf(m1, fmaxf(s[nj][0], s[nj][1]));
            m2 = fmaxf(m2, fmaxf(s[nj][2], s[nj][3]));
        }
        m1 = fmaxf(m1, __shfl_xor_sync(0xffffffffu, m1, 1));
        m1 = fmaxf(m1, __shfl_xor_sync(0xffffffffu, m1, 2));
        m2 = fmaxf(m2, __shfl_xor_sync(0xffffffffu, m2, 1));
        m2 = fmaxf(m2, __shfl_xor_sync(0xffffffffu, m2, 2));
        float s1 = 0.f, s2 = 0.f;
#pragma unroll
        for (int nj = 0; nj < 16; nj++) {
            s[nj][0] = __expf(s[nj][0] - m1); s1 += s[nj][0];
            s[nj][1] = __expf(s[nj][1] - m1); s1 += s[nj][1];
            s[nj][2] = __expf(s[nj][2] - m2); s2 += s[nj][2];
            s[nj][3] = __expf(s[nj][3] - m2); s2 += s[nj][3];
        }
        s1 += __shfl_xor_sync(0xffffffffu, s1, 1);
        s1 += __shfl_xor_sync(0xffffffffu, s1, 2);
        s2 += __shfl_xor_sync(0xffffffffu, s2, 1);
        s2 += __shfl_xor_sync(0xffffffffu, s2, 2);
        float i1 = 1.0f / s1, i2 = 1.0f / s2;

        // ---- P -> fp16 A-fragments ----
        uint32_t pa[8][4];
#pragma unroll
        for (int kt = 0; kt < 8; kt++) {
#pragma unroll
            for (int half = 0; half < 2; half++) {
                int f = 2 * kt + half;
                __half2 h01, h23;
                h01.x = __float2half_rn(s[f][0] * i1); h01.y = __float2half_rn(s[f][1] * i1);
                h23.x = __float2half_rn(s[f][2] * i2); h23.y = __float2half_rn(s[f][3] * i2);
                pa[kt][0 + 2 * half] = *(uint32_t*)&h01;
                pa[kt][1 + 2 * half] = *(uint32_t*)&h23;
            }
        }

        // ---- O = P V ----
        float o[8][4];
#pragma unroll
        for (int nj = 0; nj < 8; nj++)
#pragma unroll
            for (int e = 0; e < 4; e++) o[nj][e] = 0.f;
#pragma unroll
        for (int kt = 0; kt < 8; kt++) {
#pragma unroll
            for (int ng = 0; ng < 4; ng++) {
                uint32_t vv[4];
                ldm_x4_t(vv, vbase + (kt * 16 + vrow) * ARS + ng * 32 + vcb);
                mma_f16(o[2 * ng],     pa[kt], vv + 0);
                mma_f16(o[2 * ng + 1], pa[kt], vv + 2);
            }
        }

        // ---- write O-frags (fp16) into smem O-matrix cols [64h, 64h+64) ----
#pragma unroll
        for (int nj = 0; nj < 8; nj++) {
            int colb = (h * 64 + nj * 8 + gc2) * 2;
            __half2 h01, h23;
            h01.x = __float2half_rn(o[nj][0]); h01.y = __float2half_rn(o[nj][1]);
            h23.x = __float2half_rn(o[nj][2]); h23.y = __float2half_rn(o[nj][3]);
            *(__half2*)(sm + OFF_O + r1 * ORS + colb) = h01;
            *(__half2*)(sm + OFF_O + r2 * ORS + colb) = h23;
        }
    }
    __syncthreads();   // O-matrix complete

    // ======================= projection: dout = O @ wp^T + b ==================
    // 8 warps: wm=warp>>2 (2) x wn=warp&3 (4) -> warp tile 64x32 per n-block.
    const int pwm = wid >> 2;
    const int pwn = wid & 3;
    const uint32_t ws0 = smb + OFF_KV;             // wp tile double buffer
    const uint32_t ws1 = smb + OFF_KV + AT_B;

    auto load_wp = [&](int nb, int kc, uint32_t dst) {
        const __half* g = wp + (size_t)(nb * 128) * 512 + kc * 64;
#pragma unroll
        for (int i = 0; i < 4; i++) {
            int idx = i * 256 + tid;
            int r = idx >> 3, s = idx & 7;
            cp16(dst + r * ARS + s * 16, g + (size_t)r * 512 + s * 8);
        }
    };

    for (int nb = 0; nb < 4; nb++) {
        float acc[4][4][4];
#pragma unroll
        for (int i = 0; i < 4; i++)
#pragma unroll
            for (int j = 0; j < 4; j++)
#pragma unroll
                for (int e = 0; e < 4; e++) acc[i][j][e] = 0.f;

        load_wp(nb, 0, ws0);
        cp_commit();

        for (int kc = 0; kc < 8; kc++) {
            if (kc + 1 < 8) { load_wp(nb, kc + 1, (kc & 1) ? ws0 : ws1); cp_commit(); cp_wait<1>(); }
            else            { cp_wait<0>(); }
            __syncthreads();
            const uint32_t wt = (kc & 1) ? ws1 : ws0;

#pragma unroll
            for (int ks = 0; ks < 4; ks++) {
                const int kb = ks * 32;
                uint32_t ah[4][4], b0[2][4];
#pragma unroll
                for (int mi = 0; mi < 4; mi++)
                    ldm_x4(ah[mi], smb + OFF_O + (pwm * 64 + mi * 16 + arow) * ORS
                                   + kc * 128 + kb + acolb);
#pragma unroll
                for (int jj = 0; jj < 2; jj++)
                    ldm_x4(b0[jj], wt + (pwn * 32 + jj * 16 + brow) * ARS + kb + bkb);
#pragma unroll
                for (int mi = 0; mi < 4; mi++)
#pragma unroll
                    for (int nj = 0; nj < 4; nj++)
                        mma_f16(acc[mi][nj], ah[mi], &b0[nj >> 1][(nj & 1) * 2]);
            }
            if (kc + 1 < 8) __syncthreads();
        }

        // epilogue: bias + scatter rows through order
        float2 bv[4];
#pragma unroll
        for (int nj = 0; nj < 4; nj++)
            bv[nj] = *(const float2*)(bproj + nb * 128 + pwn * 32 + nj * 8 + gc2);
#pragma unroll
        for (int mi = 0; mi < 4; mi++) {
            int rloc = pwm * 64 + mi * 16 + gr;
            size_t ra = (size_t)ords[rloc] * 512;
            size_t rb = (size_t)ords[rloc + 8] * 512;
#pragma unroll
            for (int nj = 0; nj < 4; nj++) {
                int col = nb * 128 + pwn * 32 + nj * 8 + gc2;
                float2 lo = make_float2(acc[mi][nj][0] + bv[nj].x, acc[mi][nj][1] + bv[nj].y);
                float2 hi = make_float2(acc[mi][nj][2] + bv[nj].x, acc[mi][nj][3] + bv[nj].y);
                *(float2*)(dout + ra + col) = lo;
                *(float2*)(dout + rb + col) = hi;
            }
        }
        __syncthreads();   // wp buffers free before next nb prologue
    }
}

// ---------------------------------------------------------------------------
extern "C" void kernel_launch(void* const* d_in, const int* in_sizes, int n_in,
                              void* d_out, int out_size)
{
    const float* feat    = (const float*)d_in[0];
    const float* w_qkv   = (const float*)d_in[1];
    const float* b_qkv   = (const float*)d_in[2];
    const float* w_proj  = (const float*)d_in[3];
    const float* b_proj  = (const float*)d_in[4];
    const float* rpe     = (const float*)d_in[5];
    const int*   gcoord  = (const int*)d_in[6];
    const int*   order   = (const int*)d_in[7];
    float*       out     = (float*)d_out;

    __half *qkv, *fa, *wq, *wp;
    cudaGetSymbolAddress((void**)&qkv, g_qkv);
    cudaGetSymbolAddress((void**)&fa,  g_fa);
    cudaGetSymbolAddress((void**)&wq,  g_wq);
    cudaGetSymbolAddress((void**)&wp,  g_wp);

    cudaFuncSetAttribute(gemm_f16, cudaFuncAttributeMaxDynamicSharedMemorySize, GSMEM);
    cudaFuncSetAttribute(attn_proj, cudaFuncAttributeMaxDynamicSharedMemorySize, FSMEM);

    // 1) fp16 conversions
    tohalf_gather_k<<<NPTS * 128 / 256, 256>>>(feat, order, fa);
    tohalf_plain_k<<<(1536 * 512 / 4) / 256, 256>>>(w_qkv, wq, 1536 * 512 / 4);
    tohalf_plain_k<<<(512 * 512 / 4) / 256, 256>>>(w_proj, wp, 512 * 512 / 4);

    // 2) QKV projection (1-term) -> serialized qkv fp16 (bias added)
    gemm_f16<<<dim3(1536 / 128, NPTS / 128), 128, GSMEM>>>(
        fa, wq, b_qkv, nullptr, qkv, 1536);

    // 3) fused attention + output projection -> f32 d_out
    attn_proj<<<NPTS / PW, 256, FSMEM>>>(
        qkv, order, gcoord, rpe, wp, b_proj, out);
}

// round 16
// speedup vs baseline: 1.1251x; 1.1251x over previous
#include <cuda_runtime.h>
#include <cuda_fp16.h>
#include <stdint.h>

#define NPTS   65536
#define CCH    512
#define NH     8
#define PW     128
#define DHD    64
#define RPEN   31
#define PBND   15
#define SCALE  0.125f

// ---------------------------------------------------------------------------
// Static device scratch (fp16)
// ---------------------------------------------------------------------------
__device__ __half g_qkv[(size_t)NPTS * 1536];   // serialized qkv, single fp16
__device__ __half g_fa [(size_t)NPTS * 512];    // feat[order], single fp16
__device__ __half g_aa [(size_t)NPTS * 512];    // attn-out (point order), single fp16
__device__ __half g_wq [1536 * 512];            // w_qkv single fp16
__device__ __half g_wp [512 * 512];             // w_proj single fp16

// ---------------------------------------------------------------------------
// PTX helpers (sm_100-legal)
// ---------------------------------------------------------------------------
__device__ __forceinline__ uint32_t smem_u32(const void* p) {
    uint32_t a;
    asm("{ .reg .u64 t; cvta.to.shared.u64 t, %1; cvt.u32.u64 %0, t; }"
        : "=r"(a) : "l"(p));
    return a;
}
__device__ __forceinline__ void cp16(uint32_t dst, const void* src) {
    asm volatile("cp.async.cg.shared.global [%0], [%1], 16;"
                 :: "r"(dst), "l"(src) : "memory");
}
__device__ __forceinline__ void cp_commit() {
    asm volatile("cp.async.commit_group;" ::: "memory");
}
template <int N>
__device__ __forceinline__ void cp_wait() {
    asm volatile("cp.async.wait_group %0;" :: "n"(N) : "memory");
}
__device__ __forceinline__ void ldm_x4(uint32_t* r, uint32_t addr) {
    asm volatile("ldmatrix.sync.aligned.m8n8.x4.shared.b16 {%0,%1,%2,%3}, [%4];"
                 : "=r"(r[0]), "=r"(r[1]), "=r"(r[2]), "=r"(r[3]) : "r"(addr));
}
__device__ __forceinline__ void ldm_x4_t(uint32_t* r, uint32_t addr) {
    asm volatile("ldmatrix.sync.aligned.m8n8.x4.trans.shared.b16 {%0,%1,%2,%3}, [%4];"
                 : "=r"(r[0]), "=r"(r[1]), "=r"(r[2]), "=r"(r[3]) : "r"(addr));
}
__device__ __forceinline__ void mma_f16(float* d, const uint32_t* a, const uint32_t* b) {
    asm volatile(
        "mma.sync.aligned.m16n8k16.row.col.f32.f16.f16.f32 "
        "{%0,%1,%2,%3}, {%4,%5,%6,%7}, {%8,%9}, {%0,%1,%2,%3};"
        : "+f"(d[0]), "+f"(d[1]), "+f"(d[2]), "+f"(d[3])
        : "r"(a[0]), "r"(a[1]), "r"(a[2]), "r"(a[3]), "r"(b[0]), "r"(b[1]));
}

// ---------------------------------------------------------------------------
// Merged fp16 conversion kernel (single launch, partitioned by blockIdx.x):
//   [0, 32768)          gather-convert feat[order] -> g_fa
//   [32768, 33536)      w_qkv -> g_wq
//   [33536, 33792)      w_proj -> g_wp
// ---------------------------------------------------------------------------
#define CV_GATHER_BLKS 32768              // NPTS*128/256
#define CV_WQ_BLKS     768                // 1536*512/4/256
#define CV_WP_BLKS     256                // 512*512/4/256
#define CV_TOTAL_BLKS  (CV_GATHER_BLKS + CV_WQ_BLKS + CV_WP_BLKS)

__global__ void convert_all_k(const float* __restrict__ feat, const int* __restrict__ gidx,
                              const float* __restrict__ wq_f, const float* __restrict__ wp_f,
                              __half* __restrict__ fa, __half* __restrict__ wq,
                              __half* __restrict__ wp)
{
    int b = blockIdx.x;
    if (b < CV_GATHER_BLKS) {
        int i = b * 256 + threadIdx.x;
        int m = i >> 7;
        int c = (i & 127) << 2;
        float4 v = *(const float4*)(feat + (size_t)gidx[m] * 512 + c);
        __align__(8) __half hb[4];
        hb[0] = __float2half_rn(v.x); hb[1] = __float2half_rn(v.y);
        hb[2] = __float2half_rn(v.z); hb[3] = __float2half_rn(v.w);
        *(uint2*)(fa + (size_t)m * 512 + c) = *(uint2*)hb;
    } else {
        const float* src;
        __half* dst;
        int i;
        if (b < CV_GATHER_BLKS + CV_WQ_BLKS) {
            src = wq_f; dst = wq;
            i = (b - CV_GATHER_BLKS) * 256 + threadIdx.x;
        } else {
            src = wp_f; dst = wp;
            i = (b - CV_GATHER_BLKS - CV_WQ_BLKS) * 256 + threadIdx.x;
        }
        float4 v = *(const float4*)(src + (size_t)i * 4);
        __align__(8) __half hb[4];
        hb[0] = __float2half_rn(v.x); hb[1] = __float2half_rn(v.y);
        hb[2] = __float2half_rn(v.z); hb[3] = __float2half_rn(v.w);
        *(uint2*)(dst + (size_t)i * 4) = *(uint2*)hb;
    }
}

// ---------------------------------------------------------------------------
// fp16 1-term GEMM (R13 best-measured, byte-identical): C = A B^T + bias.
// K=512, CTA tile 128x128, BK=64, 4 warps @ 64x64, 2-stage pipeline.
// ---------------------------------------------------------------------------
#define GK       512
#define BK       64
#define NCH      (GK / BK)
#define TROW_B   144
#define TILE_B   (128 * TROW_B)
#define STAGE_B  (2 * TILE_B)
#define GSMEM    (2 * STAGE_B)

__global__ __launch_bounds__(128, 2)
void gemm_f16(const __half* __restrict__ A, const __half* __restrict__ B0,
              const float* __restrict__ bias, float* __restrict__ C,
              __half* __restrict__ Chalf, int Ntot)
{
    extern __shared__ __align__(128) char sm[];
    const uint32_t smb = smem_u32(sm);

    const int tid  = threadIdx.x;
    const int lane = tid & 31;
    const int warp = tid >> 5;
    const int wm   = warp >> 1;
    const int wn   = warp & 1;
    const int m0   = blockIdx.y * 128;
    const int n0   = blockIdx.x * 128;

    const __half* gsrc[2] = { A + (size_t)m0 * GK, B0 + (size_t)n0 * GK };

    auto load_stage = [&](int c) {
        const uint32_t sb = smb + (c & 1) * STAGE_B;
#pragma unroll
        for (int t = 0; t < 2; t++) {
            const __half* g = gsrc[t] + c * BK;
#pragma unroll
            for (int i = 0; i < 8; i++) {
                int idx = i * 128 + tid;
                int r = idx >> 3, s = idx & 7;
                cp16(sb + t * TILE_B + r * TROW_B + s * 16,
                     g + (size_t)r * GK + s * 8);
            }
        }
    };

    float acc[4][8][4];
#pragma unroll
    for (int i = 0; i < 4; i++)
#pragma unroll
        for (int j = 0; j < 8; j++)
#pragma unroll
            for (int e = 0; e < 4; e++) acc[i][j][e] = 0.f;

    const int arow  = lane & 15;
    const int acolb = (lane >> 4) * 16;
    const int brow  = (lane & 7) + (lane >> 4) * 8;
    const int bkb   = ((lane >> 3) & 1) * 16;

    load_stage(0);
    cp_commit();

    for (int c = 0; c < NCH; c++) {
        if (c + 1 < NCH) { load_stage(c + 1); cp_commit(); cp_wait<1>(); }
        else             { cp_wait<0>(); }
        __syncthreads();

        const uint32_t sb  = smb + (c & 1) * STAGE_B;
        const uint32_t sA  = sb;
        const uint32_t sB0 = sb + TILE_B;

#pragma unroll
        for (int ks = 0; ks < 4; ks++) {
            const int kb = ks * 32;
            uint32_t ah[4][4], b0[4][4];
#pragma unroll
            for (int mi = 0; mi < 4; mi++)
                ldm_x4(ah[mi], sA + (wm * 64 + mi * 16 + arow) * TROW_B + kb + acolb);
#pragma unroll
            for (int jj = 0; jj < 4; jj++)
                ldm_x4(b0[jj], sB0 + (wn * 64 + jj * 16 + brow) * TROW_B + kb + bkb);
#pragma unroll
            for (int mi = 0; mi < 4; mi++)
#pragma unroll
                for (int nj = 0; nj < 8; nj++)
                    mma_f16(acc[mi][nj], ah[mi], &b0[nj >> 1][(nj & 1) * 2]);
        }
        if (c + 1 < NCH) __syncthreads();
    }

    const int gr = lane >> 2;
    const int gc = (lane & 3) * 2;
    float2 bv[8];
#pragma unroll
    for (int nj = 0; nj < 8; nj++)
        bv[nj] = *(const float2*)(bias + n0 + wn * 64 + nj * 8 + gc);

    if (Chalf) {
#pragma unroll
        for (int mi = 0; mi < 4; mi++) {
            int rowa = m0 + wm * 64 + mi * 16 + gr;
#pragma unroll
            for (int nj = 0; nj < 8; nj++) {
                int col = n0 + wn * 64 + nj * 8 + gc;
                __half2 h01, h23;
                h01.x = __float2half_rn(acc[mi][nj][0] + bv[nj].x);
                h01.y = __float2half_rn(acc[mi][nj][1] + bv[nj].y);
                h23.x = __float2half_rn(acc[mi][nj][2] + bv[nj].x);
                h23.y = __float2half_rn(acc[mi][nj][3] + bv[nj].y);
                *(__half2*)(Chalf + (size_t)rowa * Ntot + col)       = h01;
                *(__half2*)(Chalf + (size_t)(rowa + 8) * Ntot + col) = h23;
            }
        }
    } else {
#pragma unroll
        for (int mi = 0; mi < 4; mi++) {
            int rowa = m0 + wm * 64 + mi * 16 + gr;
#pragma unroll
            for (int nj = 0; nj < 8; nj++) {
                int col = n0 + wn * 64 + nj * 8 + gc;
                float2 lo = make_float2(acc[mi][nj][0] + bv[nj].x, acc[mi][nj][1] + bv[nj].y);
                float2 hi = make_float2(acc[mi][nj][2] + bv[nj].x, acc[mi][nj][3] + bv[nj].y);
                *(float2*)(C + (size_t)rowa * Ntot + col)       = lo;
                *(float2*)(C + (size_t)(rowa + 8) * Ntot + col) = hi;
            }
        }
    }
}

// ---------------------------------------------------------------------------
// fp16 mma attention per (window, head) — R13 best-measured, byte-identical.
// Single-term QK^T and PV; RPE via packed-byte SIMD; register scatter epilogue.
// ---------------------------------------------------------------------------
#define ARS      144
#define AT_B     (128 * ARS)
#define OFF_Q    0
#define OFF_K    (1 * AT_B)
#define OFF_V    (2 * AT_B)
#define OFF_RPE  (3 * AT_B)
#define OFF_GC   (OFF_RPE + 96 * 4)
#define OFF_ORD  (OFF_GC + 128 * 4)
#define ASMEM    (OFF_ORD + 128 * 4)

__global__ __launch_bounds__(256, 2)
void attn_mma(const __half* __restrict__ qkv,
              const int* __restrict__ order, const int* __restrict__ gcoord,
              const float* __restrict__ rpe, __half* __restrict__ oa)
{
    extern __shared__ __align__(128) char sm[];
    const uint32_t smb = smem_u32(sm);
    float*    rpeS = (float*)(sm + OFF_RPE);
    uint32_t* pcs  = (uint32_t*)(sm + OFF_GC);
    int*      ords = (int*)(sm + OFF_ORD);

    const int w    = blockIdx.x;
    const int hh   = blockIdx.y;
    const int tid  = threadIdx.x;
    const int lane = tid & 31;
    const int wid  = tid >> 5;
    const int wb   = w * PW;

    const __half* base = qkv + (size_t)wb * 1536 + hh * 64;
    const __half* srcp[3] = { base, base + 512, base + 1024 };
#pragma unroll
    for (int m = 0; m < 3; m++) {
        uint32_t dstb = smb + m * AT_B;
#pragma unroll
        for (int i = 0; i < 4; i++) {
            int idx = i * 256 + tid;
            int r = idx >> 3, s = idx & 7;
            cp16(dstb + r * ARS + s * 16, srcp[m] + (size_t)r * 1536 + s * 8);
        }
    }
    cp_commit();

    for (int i = tid; i < 128; i += 256) {
        int g = order[wb + i];
        ords[i] = g;
        uint32_t x = (uint32_t)gcoord[g * 3 + 0] & 0xFF;
        uint32_t y = (uint32_t)gcoord[g * 3 + 1] & 0xFF;
        uint32_t z = (uint32_t)gcoord[g * 3 + 2] & 0xFF;
        pcs[i] = x | (y << 8) | (z << 16);
    }
    for (int i = tid; i < 3 * RPEN; i += 256) rpeS[i] = rpe[i * NH + hh];
    cp_wait<0>();
    __syncthreads();

    const int w16   = wid * 16;
    const int arow  = lane & 15;
    const int acolb = (lane >> 4) * 16;
    const int brow  = (lane & 7) + (lane >> 4) * 8;
    const int bkb   = ((lane >> 3) & 1) * 16;

    uint32_t q4[4][4];
#pragma unroll
    for (int ks = 0; ks < 4; ks++)
        ldm_x4(q4[ks], smb + OFF_Q + (w16 + arow) * ARS + ks * 32 + acolb);

    float s[16][4];
#pragma unroll
    for (int nj = 0; nj < 16; nj++)
#pragma unroll
        for (int e = 0; e < 4; e++) s[nj][e] = 0.f;

#pragma unroll
    for (int ks = 0; ks < 4; ks++) {
#pragma unroll
        for (int ng = 0; ng < 8; ng++) {
            uint32_t kk[4];
            ldm_x4(kk, smb + OFF_K + (ng * 16 + brow) * ARS + ks * 32 + bkb);
            mma_f16(s[2 * ng],     q4[ks], kk + 0);
            mma_f16(s[2 * ng + 1], q4[ks], kk + 2);
        }
    }

    const int gr  = lane >> 2;
    const int gc2 = (lane & 3) * 2;
    const int r1  = w16 + gr, r2 = r1 + 8;
    const uint32_t pq1 = pcs[r1], pq2 = pcs[r2];
    const uint32_t NEG15 = 0xF1F1F1F1u, POS15 = 0x0F0F0F0Fu;

#pragma unroll
    for (int nj = 0; nj < 16; nj++) {
        int c0 = nj * 8 + gc2;
#pragma unroll
        for (int cc = 0; cc < 2; cc++) {
            uint32_t pk = pcs[c0 + cc];
            uint32_t da = __vadd4(__vmins4(__vmaxs4(__vsubss4(pq1, pk), NEG15), POS15), POS15);
            uint32_t db = __vadd4(__vmins4(__vmaxs4(__vsubss4(pq2, pk), NEG15), POS15), POS15);
            float ba = rpeS[da & 0xFF] + rpeS[((da >> 8) & 0xFF) + RPEN]
                     + rpeS[((da >> 16) & 0xFF) + 2 * RPEN];
            float bb = rpeS[db & 0xFF] + rpeS[((db >> 8) & 0xFF) + RPEN]
                     + rpeS[((db >> 16) & 0xFF) + 2 * RPEN];
            s[nj][cc]     = s[nj][cc]     * SCALE + ba;
            s[nj][2 + cc] = s[nj][2 + cc] * SCALE + bb;
        }
    }

    float m1 = -1e30f, m2 = -1e30f;
#pragma unroll
    for (int nj = 0; nj < 16; nj++) {
        m1 = fmaxf(m1, fmaxf(s[nj][0], s[nj][1]));
        m2 = fmaxf(m2, fmaxf(s[nj][2], s[nj][3]));
    }
    m1 = fmaxf(m1, __shfl_xor_sync(0xffffffffu, m1, 1));
    m1 = fmaxf(m1, __shfl_xor_sync(0xffffffffu, m1, 2));
    m2 = fmaxf(m2, __shfl_xor_sync(0xffffffffu, m2, 1));
    m2 = fmaxf(m2, __shfl_xor_sync(0xffffffffu, m2, 2));
    float s1 = 0.f, s2 = 0.f;
#pragma unroll
    for (int nj = 0; nj < 16; nj++) {
        s[nj][0] = __expf(s[nj][0] - m1); s1 += s[nj][0];
        s[nj][1] = __expf(s[nj][1] - m1); s1 += s[nj][1];
        s[nj][2] = __expf(s[nj][2] - m2); s2 += s[nj][2];
        s[nj][3] = __expf(s[nj][3] - m2); s2 += s[nj][3];
    }
    s1 += __shfl_xor_sync(0xffffffffu, s1, 1);
    s1 += __shfl_xor_sync(0xffffffffu, s1, 2);
    s2 += __shfl_xor_sync(0xffffffffu, s2, 1);
    s2 += __shfl_xor_sync(0xffffffffu, s2, 2);
    float i1 = 1.0f / s1, i2 = 1.0f / s2;

    uint32_t pa[8][4];
#pragma unroll
    for (int kt = 0; kt < 8; kt++) {
#pragma unroll
        for (int half = 0; half < 2; half++) {
            int f = 2 * kt + half;
            __half2 h01, h23;
            h01.x = __float2half_rn(s[f][0] * i1); h01.y = __float2half_rn(s[f][1] * i1);
            h23.x = __float2half_rn(s[f][2] * i2); h23.y = __float2half_rn(s[f][3] * i2);
            pa[kt][0 + 2 * half] = *(uint32_t*)&h01;
            pa[kt][1 + 2 * half] = *(uint32_t*)&h23;
        }
    }

    float o[8][4];
#pragma unroll
    for (int nj = 0; nj < 8; nj++)
#pragma unroll
        for (int e = 0; e < 4; e++) o[nj][e] = 0.f;

    const int vrow = ((lane >> 3) & 1) * 8 + (lane & 7);
    const int vcb  = (lane >> 4) * 16;
#pragma unroll
    for (int kt = 0; kt < 8; kt++) {
#pragma unroll
        for (int ng = 0; ng < 4; ng++) {
            uint32_t vv[4];
            ldm_x4_t(vv, smb + OFF_V + (kt * 16 + vrow) * ARS + ng * 32 + vcb);
            mma_f16(o[2 * ng],     pa[kt], vv + 0);
            mma_f16(o[2 * ng + 1], pa[kt], vv + 2);
        }
    }

    const int d1 = ords[r1], d2 = ords[r2];
#pragma unroll
    for (int nj = 0; nj < 8; nj++) {
        int col = nj * 8 + gc2;
        __half2 h01, h23;
        h01.x = __float2half_rn(o[nj][0]); h01.y = __float2half_rn(o[nj][1]);
        h23.x = __float2half_rn(o[nj][2]); h23.y = __float2half_rn(o[nj][3]);
        *(__half2*)(oa + (size_t)d1 * 512 + hh * 64 + col) = h01;
        *(__half2*)(oa + (size_t)d2 * 512 + hh * 64 + col) = h23;
    }
}

// ---------------------------------------------------------------------------
extern "C" void kernel_launch(void* const* d_in, const int* in_sizes, int n_in,
                              void* d_out, int out_size)
{
    const float* feat    = (const float*)d_in[0];
    const float* w_qkv   = (const float*)d_in[1];
    const float* b_qkv   = (const float*)d_in[2];
    const float* w_proj  = (const float*)d_in[3];
    const float* b_proj  = (const float*)d_in[4];
    const float* rpe     = (const float*)d_in[5];
    const int*   gcoord  = (const int*)d_in[6];
    const int*   order   = (const int*)d_in[7];
    float*       out     = (float*)d_out;

    __half *qkv, *fa, *aa, *wq, *wp;
    cudaGetSymbolAddress((void**)&qkv, g_qkv);
    cudaGetSymbolAddress((void**)&fa,  g_fa);
    cudaGetSymbolAddress((void**)&aa,  g_aa);
    cudaGetSymbolAddress((void**)&wq,  g_wq);
    cudaGetSymbolAddress((void**)&wp,  g_wp);

    cudaFuncSetAttribute(gemm_f16, cudaFuncAttributeMaxDynamicSharedMemorySize, GSMEM);
    cudaFuncSetAttribute(attn_mma, cudaFuncAttributeMaxDynamicSharedMemorySize, ASMEM);

    // 1) all fp16 conversions in ONE launch
    convert_all_k<<<CV_TOTAL_BLKS, 256>>>(feat, order, w_qkv, w_proj, fa, wq, wp);

    // 2) QKV projection (1-term) -> serialized qkv fp16 (bias added)
    gemm_f16<<<dim3(1536 / 128, NPTS / 128), 128, GSMEM>>>(
        fa, wq, b_qkv, nullptr, qkv, 1536);

    // 3) fp16 mma attention; fp16 output scattered to point order
    attn_mma<<<dim3(NPTS / PW, NH), 256, ASMEM>>>(
        qkv, order, gcoord, rpe, aa);

    // 4) Output projection (1-term) -> f32 d_out
    gemm_f16<<<dim3(512 / 128, NPTS / 128), 128, GSMEM>>>(
        aa, wp, b_proj, out, nullptr, 512);
}